// round 17
// baseline (speedup 1.0000x reference)
#include <cuda_runtime.h>
#include <cuda_bf16.h>
#include <cuda_fp16.h>
#include <math.h>
#include <stdint.h>

#define HID   1024
#define EMB   512
#define TLEN  2048
#define G4    4096
#define NCTA  128
#define OSIZE 32000
#define K2E   (2*EMB)
#define K2H   (2*HID)
#define NREP  8

typedef unsigned long long ull;

// ---------------- scratch ----------------
__device__ float g_xg_enc[(size_t)TLEN * G4];
__device__ float g_xg_dec[(size_t)TLEN * G4];
__device__ float g_hrep[2][NREP][HID];
__device__ float g_cenc[HID];
__device__ float g_czero[HID];
__device__ int   g_decidx[TLEN];
__device__ unsigned g_ctr;
__device__ __half g_A2e[(size_t)TLEN * K2E];
__device__ __half g_A2d[(size_t)TLEN * K2E];
__device__ __half g_W2e[(size_t)G4 * K2E];
__device__ __half g_W2d[(size_t)G4 * K2E];
__device__ __half g_B2o[(size_t)OSIZE * K2H];
__device__ __half g_A2h[(size_t)TLEN * K2H];

// ---------------- helpers ----------------
__device__ __forceinline__ uint32_t s2u(const void* p) {
    return (uint32_t)__cvta_generic_to_shared(p);
}
__device__ __forceinline__ void cp16(uint32_t dst, const void* src) {
    asm volatile("cp.async.cg.shared.global [%0], [%1], 16;" :: "r"(dst), "l"(src) : "memory");
}
#define CP_COMMIT() asm volatile("cp.async.commit_group;" ::: "memory")
#define CP_WAIT2()  asm volatile("cp.async.wait_group 2;" ::: "memory")

#define LDSM_X4(r0, r1, r2, r3, addr) \
    asm volatile("ldmatrix.sync.aligned.m8n8.x4.shared.b16 {%0,%1,%2,%3}, [%4];" \
                 : "=r"(r0), "=r"(r1), "=r"(r2), "=r"(r3) : "r"(addr))

#define MMA_F16(d, a, b0, b1) \
    asm volatile("mma.sync.aligned.m16n8k16.row.col.f32.f16.f16.f32 " \
                 "{%0,%1,%2,%3}, {%4,%5,%6,%7}, {%8,%9}, {%0,%1,%2,%3};" \
                 : "+f"((d)[0]), "+f"((d)[1]), "+f"((d)[2]), "+f"((d)[3]) \
                 : "r"((a)[0]), "r"((a)[1]), "r"((a)[2]), "r"((a)[3]), \
                   "r"(b0), "r"(b1))

#define FMA2(acc, w, h) \
    asm("fma.rn.f32x2 %0, %1, %2, %0;" : "+l"(acc) : "l"(w), "l"(h))
#define ADD2(d, a, b) \
    asm("add.rn.f32x2 %0, %1, %2;" : "=l"(d) : "l"(a), "l"(b))

__device__ __forceinline__ float tanh_apx(float x) {
    float r;
    asm("tanh.approx.f32 %0, %1;" : "=f"(r) : "f"(x));
    return r;
}
__device__ __forceinline__ float sigf(float x) {
    return fmaf(tanh_apx(0.5f * x), 0.5f, 0.5f);
}

static __device__ __forceinline__ uint32_t sw128(uint32_t off) {
    return off ^ ((off >> 3) & 0x70);
}

// ---------------- init kernels ----------------
__global__ void init0_kernel(const int* __restrict__ gt) {
    int i = blockIdx.x * blockDim.x + threadIdx.x;
    if (i == 0) g_ctr = 0u;
    if (i < HID) {
        g_czero[i] = 0.f;
#pragma unroll
        for (int r = 0; r < NREP; r++) {
            g_hrep[0][r][i] = 0.f;
            g_hrep[1][r][i] = 0.f;
        }
    }
    if (i < TLEN) g_decidx[i] = (i == 0) ? 1 : gt[i - 1];
}
__global__ void init1_kernel() {
    int i = blockIdx.x * blockDim.x + threadIdx.x;
    if (i == 0) g_ctr = 0u;
    if (i < HID) {
        float v = g_cenc[i];
#pragma unroll
        for (int r = 0; r < NREP; r++) g_hrep[0][r][i] = v;
    }
}

// ---------------- fp16 [hi|lo] split (A side; optional gather) ----------------
__global__ __launch_bounds__(256)
void conv_split_f16(const float* __restrict__ src, const int* __restrict__ idx,
                    __half* __restrict__ dst, int K, long total)
{
    long i = ((long)blockIdx.x * blockDim.x + threadIdx.x) * 4;
    if (i >= total) return;
    int r = (int)(i / K);
    int k = (int)(i % K);
    int srow = idx ? idx[r] : r;
    float4 v = *(const float4*)(src + (size_t)srow * K + k);

    __half hx = __float2half_rn(v.x), hy = __float2half_rn(v.y);
    __half hz = __float2half_rn(v.z), hw = __float2half_rn(v.w);
    __half lx = __float2half_rn(v.x - __half2float(hx));
    __half ly = __float2half_rn(v.y - __half2float(hy));
    __half lz = __float2half_rn(v.z - __half2float(hz));
    __half lw = __float2half_rn(v.w - __half2float(hw));

    size_t base = (size_t)r * 2 * K;
    *(__half2*)(dst + base + k)         = {hx, hy};
    *(__half2*)(dst + base + k + 2)     = {hz, hw};
    *(__half2*)(dst + base + K + k)     = {lx, ly};
    *(__half2*)(dst + base + K + k + 2) = {lz, lw};
}

// ---------------- fp16 duplicate (B side): dst row = [w | w] ----------------
__global__ __launch_bounds__(256)
void conv_dup_f16(const float* __restrict__ src, __half* __restrict__ dst,
                  int K, long total)
{
    long i = ((long)blockIdx.x * blockDim.x + threadIdx.x) * 4;
    if (i >= total) return;
    int r = (int)(i / K);
    int k = (int)(i % K);
    float4 v = *(const float4*)(src + (size_t)r * K + k);
    __half2 h01 = {__float2half_rn(v.x), __float2half_rn(v.y)};
    __half2 h23 = {__float2half_rn(v.z), __float2half_rn(v.w)};
    size_t base = (size_t)r * 2 * K;
    *(__half2*)(dst + base + k)         = h01;
    *(__half2*)(dst + base + k + 2)     = h23;
    *(__half2*)(dst + base + K + k)     = h01;
    *(__half2*)(dst + base + K + k + 2) = h23;
}

// ---------------- fp16 mma.sync GEMM: C[M,N]=A[M,K]*B[N,K]^T + bias ----------------
#define ASTG 16384
#define BSTG 32768
#define STG  (ASTG + BSTG)
#define GEMM_SMEM (4 * STG + 2048)

__global__ __launch_bounds__(256, 1)
void gemm_mma2(const __half* __restrict__ Ag, const __half* __restrict__ Bg,
               const float* __restrict__ b1, const float* __restrict__ b2,
               float* __restrict__ C, int Mt, int K3, int Ncols, int GN)
{
    extern __shared__ char smem_raw[];
    const uint32_t sraw = s2u(smem_raw);
    const uint32_t sb0  = (sraw + 1023u) & ~1023u;
    float* sbias = (float*)(smem_raw + (sb0 - sraw) + 4 * STG);

    const int tid  = threadIdx.x;
    const int wid  = tid >> 5;
    const int lane = tid & 31;
    const int NC   = K3 >> 6;

    int gw  = Mt * GN;
    int gid = blockIdx.x / gw;
    int rem = blockIdx.x % gw;
    int m0 = (rem % Mt) * 128;
    int n0 = (gid * GN + rem / Mt) * 256;

    sbias[tid] = b1[n0 + tid] + (b2 ? b2[n0 + tid] : 0.f);

    const int rbase = tid >> 3;
    const int seg   = tid & 7;
    uint32_t swA[4], swB[8];
#pragma unroll
    for (int r = 0; r < 4; r++)
        swA[r] = sw128((uint32_t)(rbase + r * 32) * 128u + (uint32_t)seg * 16u);
#pragma unroll
    for (int r = 0; r < 8; r++)
        swB[r] = sw128((uint32_t)(rbase + r * 32) * 128u + (uint32_t)seg * 16u);
    const __half* Asrc = Ag + (size_t)(m0 + rbase) * K3 + seg * 8;
    const __half* Bsrc = Bg + (size_t)(n0 + rbase) * K3 + seg * 8;
    const size_t rstride = (size_t)32 * K3;

    const int wm = wid & 1;
    const int wn = wid >> 1;
    const int arow = wm * 64 + (lane & 15);
    const uint32_t akoff = (uint32_t)(lane >> 4) * 16u;
    const int brow = wn * 64 + ((lane >> 4) & 1) * 8 + (lane & 7);
    const uint32_t bkoff = (uint32_t)((lane >> 3) & 1) * 16u;

    float d[4][8][4];
#pragma unroll
    for (int i = 0; i < 4; i++)
#pragma unroll
        for (int j = 0; j < 8; j++)
#pragma unroll
            for (int q = 0; q < 4; q++) d[i][j][q] = 0.f;

#pragma unroll
    for (int c = 0; c < 3; c++) {
        uint32_t ab = sb0 + c * STG;
        uint32_t bb = ab + ASTG;
#pragma unroll
        for (int r = 0; r < 4; r++)
            cp16(ab + swA[r], Asrc + r * rstride + (size_t)c * 64);
#pragma unroll
        for (int r = 0; r < 8; r++)
            cp16(bb + swB[r], Bsrc + r * rstride + (size_t)c * 64);
        CP_COMMIT();
    }

    for (int c = 0; c < NC; ++c) {
        CP_WAIT2();
        __syncthreads();

        int slot = c & 3;
        uint32_t sA = sb0 + slot * STG;
        uint32_t sB = sA + ASTG;

#pragma unroll
        for (int ks = 0; ks < 4; ks++) {
            uint32_t kb = (uint32_t)ks * 32u;
            uint32_t a[4][4], bq[4][4];
#pragma unroll
            for (int i = 0; i < 4; i++) {
                uint32_t addr = sA + sw128((uint32_t)(arow + 16 * i) * 128u + kb + akoff);
                LDSM_X4(a[i][0], a[i][1], a[i][2], a[i][3], addr);
            }
#pragma unroll
            for (int j = 0; j < 4; j++) {
                uint32_t addr = sB + sw128((uint32_t)(brow + 16 * j) * 128u + kb + bkoff);
                LDSM_X4(bq[j][0], bq[j][1], bq[j][2], bq[j][3], addr);
            }
#pragma unroll
            for (int i = 0; i < 4; i++) {
#pragma unroll
                for (int j = 0; j < 4; j++) {
                    MMA_F16(d[i][2 * j],     a[i], bq[j][0], bq[j][1]);
                    MMA_F16(d[i][2 * j + 1], a[i], bq[j][2], bq[j][3]);
                }
            }
        }

        int cl = c + 3;
        if (cl < NC) {
            int ls = cl & 3;
            uint32_t ab = sb0 + ls * STG;
            uint32_t bb = ab + ASTG;
#pragma unroll
            for (int r = 0; r < 4; r++)
                cp16(ab + swA[r], Asrc + r * rstride + (size_t)cl * 64);
#pragma unroll
            for (int r = 0; r < 8; r++)
                cp16(bb + swB[r], Bsrc + r * rstride + (size_t)cl * 64);
            CP_COMMIT();
        }
    }

    const int erow = lane >> 2;
    const int ecol = (lane & 3) * 2;
#pragma unroll
    for (int i = 0; i < 4; i++) {
        int r0 = m0 + wm * 64 + i * 16 + erow;
#pragma unroll
        for (int j = 0; j < 8; j++) {
            int cbase = wn * 64 + j * 8 + ecol;
            float bz0 = sbias[cbase], bz1 = sbias[cbase + 1];
            float2 v0 = { d[i][j][0] + bz0, d[i][j][1] + bz1 };
            float2 v1 = { d[i][j][2] + bz0, d[i][j][3] + bz1 };
            *(float2*)(C + (size_t)r0 * Ncols + n0 + cbase)       = v0;
            *(float2*)(C + (size_t)(r0 + 8) * Ncols + n0 + cbase) = v1;
        }
    }
}

// ---------------- persistent LSTM scan (unchanged from R16) ----------------
__global__ __launch_bounds__(256, 1)
void lstm_seq(const float* __restrict__ Whh, const float* __restrict__ xg,
              const float* __restrict__ c0, __half* __restrict__ a2h_out,
              float* __restrict__ c_out, int T)
{
    __shared__ ulonglong2 sh2[256];
    __shared__ float sp[8][33];

    const int tid  = threadIdx.x;
    const int warp = tid >> 5;
    const int lane = tid & 31;
    const int cta  = blockIdx.x;
    const int g    = lane >> 3;
    const int jj   = lane & 7;
    const int row  = g * HID + cta * 8 + jj;
    const int u8   = cta * 8 + (lane & 7);
    const int rep0 = lane >> 3;

    ulonglong2 w2[32];
    {
        const ulonglong2* wp =
            (const ulonglong2*)(Whh + (size_t)row * HID + warp * 128);
#pragma unroll
        for (int i = 0; i < 32; i++) w2[i] = wp[i];
    }

    float creg = 0.f;
    if (warp == 0) creg = c0[u8];
    unsigned* ctr = &g_ctr;

    const float* xgp = xg + (size_t)g * HID + cta * 8 + jj;
    float xgv_next = 0.f;
    if (tid < 32) xgv_next = __ldg(xgp);

    const ulonglong2* hsrc0 = ((const ulonglong2*)g_hrep[0][cta & 7]) + tid;
    const ulonglong2* hsrc1 = ((const ulonglong2*)g_hrep[1][cta & 7]) + tid;

    float p_hnew = 0.f;

    for (int t = 0; t < T; ++t) {
        sh2[tid] = __ldcg((t & 1) ? hsrc1 : hsrc0);
        float xgv = xgv_next;
        if (tid < 32 && t + 1 < T)
            xgv_next = __ldg(xgp + (size_t)(t + 1) * G4);

        if (a2h_out && warp == 0 && lane < 8 && t > 0) {
            __half hhi = __float2half_rn(p_hnew);
            __half hlo = __float2half_rn(p_hnew - __half2float(hhi));
            size_t rb = (size_t)(t - 1) * K2H;
            a2h_out[rb + u8]       = hhi;
            a2h_out[rb + HID + u8] = hlo;
        }
        __syncwarp();

        ull a0 = 0, a1 = 0, a2 = 0, a3 = 0;
        const ulonglong2* hp = sh2 + warp * 32;
#pragma unroll
        for (int j = 0; j < 32; j += 2) {
            ulonglong2 ha = hp[j];
            ulonglong2 hb = hp[j + 1];
            FMA2(a0, w2[j].x, ha.x);
            FMA2(a1, w2[j].y, ha.y);
            FMA2(a2, w2[j + 1].x, hb.x);
            FMA2(a3, w2[j + 1].y, hb.y);
        }
        ull t01, t23, tt;
        ADD2(t01, a0, a1);
        ADD2(t23, a2, a3);
        ADD2(tt, t01, t23);
        uint32_t lo, hi;
        asm("mov.b64 {%0, %1}, %2;" : "=r"(lo), "=r"(hi) : "l"(tt));
        sp[warp][lane] = __uint_as_float(lo) + __uint_as_float(hi);
        __syncthreads();

        if (warp == 0) {
            float s = xgv;
#pragma unroll
            for (int w = 0; w < 8; w++) s += sp[w][lane];
            float act = (g == 2) ? tanh_apx(s) : sigf(s);
            float ai = __shfl_sync(0xffffffffu, act, lane & 7);
            float af = __shfl_sync(0xffffffffu, act, 8 + (lane & 7));
            float az = __shfl_sync(0xffffffffu, act, 16 + (lane & 7));
            float ao = __shfl_sync(0xffffffffu, act, 24 + (lane & 7));

            creg = af * creg + ai * az;
            float hnew = ao * tanh_apx(creg);
            p_hnew = hnew;

            float* outb = &g_hrep[(t + 1) & 1][0][0];
            outb[(size_t)rep0 * HID + u8]       = hnew;
            outb[(size_t)(rep0 + 4) * HID + u8] = hnew;

            __syncwarp();
            if (lane == 0) {
                unsigned old;
                asm volatile("atom.acq_rel.gpu.global.add.u32 %0, [%1], 1;"
                             : "=r"(old) : "l"(ctr) : "memory");
                unsigned tgt = (unsigned)(t + 1) * (unsigned)NCTA;
                if (old + 1u != tgt) {
                    unsigned v;
                    do {
                        asm volatile("ld.acquire.gpu.global.u32 %0, [%1];"
                                     : "=r"(v) : "l"(ctr) : "memory");
                    } while (v < tgt);
                }
            }
        }
        __syncthreads();
    }

    if (warp == 0 && lane < 8) {
        if (a2h_out) {
            __half hhi = __float2half_rn(p_hnew);
            __half hlo = __float2half_rn(p_hnew - __half2float(hhi));
            size_t rb = (size_t)(T - 1) * K2H;
            a2h_out[rb + u8]       = hhi;
            a2h_out[rb + HID + u8] = hlo;
        }
        if (c_out) c_out[u8] = creg;
    }
}

// ---------------- launch ----------------
static void launch_gemm(const __half* A, const __half* B,
                        const float* b1, const float* b2, float* C,
                        int M, int N, int K2, int GN)
{
    int Mt = M / 128, Nt = N / 256;
    cudaFuncSetAttribute(gemm_mma2, cudaFuncAttributeMaxDynamicSharedMemorySize, GEMM_SMEM);
    gemm_mma2<<<Mt * Nt, 256, GEMM_SMEM>>>(A, B, b1, b2, C, Mt, K2, N, GN);
}

extern "C" void kernel_launch(void* const* d_in, const int* in_sizes, int n_in,
                              void* d_out, int out_size)
{
    const int*   e1       = (const int*)d_in[0];
    const int*   gt       = (const int*)d_in[1];
    const float* emb_i    = (const float*)d_in[2];
    const float* emb_o    = (const float*)d_in[3];
    const float* enc_Wih  = (const float*)d_in[4];
    const float* enc_Whh  = (const float*)d_in[5];
    const float* enc_bih  = (const float*)d_in[6];
    const float* enc_bhh  = (const float*)d_in[7];
    const float* dec_Wih  = (const float*)d_in[8];
    const float* dec_Whh  = (const float*)d_in[9];
    const float* dec_bih  = (const float*)d_in[10];
    const float* dec_bhh  = (const float*)d_in[11];
    const float* outW     = (const float*)d_in[12];
    const float* outb     = (const float*)d_in[13];
    float*       out      = (float*)d_out;

    float *xge, *xgd, *cenc, *czero;
    int* didx;
    __half *a2e, *a2d, *w2e, *w2d, *b2o, *a2h;
    cudaGetSymbolAddress((void**)&xge,   g_xg_enc);
    cudaGetSymbolAddress((void**)&xgd,   g_xg_dec);
    cudaGetSymbolAddress((void**)&cenc,  g_cenc);
    cudaGetSymbolAddress((void**)&czero, g_czero);
    cudaGetSymbolAddress((void**)&didx,  g_decidx);
    cudaGetSymbolAddress((void**)&a2e,   g_A2e);
    cudaGetSymbolAddress((void**)&a2d,   g_A2d);
    cudaGetSymbolAddress((void**)&w2e,   g_W2e);
    cudaGetSymbolAddress((void**)&w2d,   g_W2d);
    cudaGetSymbolAddress((void**)&b2o,   g_B2o);
    cudaGetSymbolAddress((void**)&a2h,   g_A2h);

    init0_kernel<<<8, 256>>>(gt);

    // conversions (all fp16 2-split now)
    {
        long t1 = (long)G4 * EMB;
        conv_dup_f16<<<(int)(t1 / 4 / 256), 256>>>(enc_Wih, w2e, EMB, t1);
        conv_dup_f16<<<(int)(t1 / 4 / 256), 256>>>(dec_Wih, w2d, EMB, t1);
        long t2 = (long)OSIZE * HID;
        conv_dup_f16<<<(int)(t2 / 4 / 256), 256>>>(outW, b2o, HID, t2);
        long t3 = (long)TLEN * EMB;
        conv_split_f16<<<(int)(t3 / 4 / 256), 256>>>(emb_i, e1,   a2e, EMB, t3);
        conv_split_f16<<<(int)(t3 / 4 / 256), 256>>>(emb_o, didx, a2d, EMB, t3);
    }

    // x-gates: fp16 2-split, K = 1024
    launch_gemm(a2e, w2e, enc_bih, enc_bhh, xge, TLEN, G4, K2E, 16);
    launch_gemm(a2d, w2d, dec_bih, dec_bhh, xgd, TLEN, G4, K2E, 16);

    // encoder scan (keeps final cell state)
    lstm_seq<<<NCTA, 256>>>(enc_Whh, xge, czero, nullptr, cenc, TLEN);
    init1_kernel<<<4, 256>>>();
    // decoder scan — writes fp16 [hi|lo] h panel directly
    lstm_seq<<<NCTA, 256>>>(dec_Whh, xgd, cenc, a2h, nullptr, TLEN);

    // logits: fp16 2-split, K = 2048
    launch_gemm(a2h, b2o, outb, nullptr, out, TLEN, OSIZE, K2H, 25);
}